// round 1
// baseline (speedup 1.0000x reference)
#include <cuda_runtime.h>
#include <cstdint>

#define B 8
#define N 32768
#define K 1024
#define C 128
#define CSIZE 8                  // CTAs per cluster (one cluster per batch)
#define T 512                    // threads per CTA
#define PPT (N / (CSIZE * T))    // 8 points per thread
#define NW (T / 32)              // 16 warps per CTA

// FPS-selected indices, [B][K]
__device__ int g_fps_idx[B * K];

struct alignas(32) Tup {
    unsigned d;      // fp32 bits of best (updated) min-dist
    int i;           // point index
    float x, y, z;   // coords of that point
    unsigned pad[3];
};

__device__ __forceinline__ unsigned smem_u32(const void* p) {
    return (unsigned)__cvta_generic_to_shared(p);
}

__device__ __forceinline__ unsigned mapa_u32(unsigned addr, unsigned rank) {
    unsigned r;
    asm("mapa.shared::cluster.u32 %0, %1, %2;" : "=r"(r) : "r"(addr), "r"(rank));
    return r;
}

__device__ __forceinline__ void st_cluster_u32(unsigned addr, unsigned v) {
    asm volatile("st.shared::cluster.u32 [%0], %1;" :: "r"(addr), "r"(v));
}

__device__ __forceinline__ void cluster_sync_all() {
    asm volatile("barrier.cluster.arrive.aligned;" ::: "memory");
    asm volatile("barrier.cluster.wait.aligned;" ::: "memory");
}

__global__ void __cluster_dims__(CSIZE, 1, 1) __launch_bounds__(T, 1)
fps_kernel(const float* __restrict__ xyz) {
    __shared__ Tup s_warp[NW];
    __shared__ Tup s_cl[2][CSIZE];   // double-buffered cross-CTA candidate slots

    const int t = threadIdx.x;
    const int lane = t & 31;
    const int w = t >> 5;
    const int blk = blockIdx.x;
    const int b = blk / CSIZE;       // batch
    const int r = blk % CSIZE;       // cluster rank (clusters are contiguous in x)

    const float* xb = xyz + (size_t)b * 3 * N;

    // Register-resident point slice + running min-dist
    float px[PPT], py[PPT], pz[PPT], pd[PPT];
    const int base = r * (N / CSIZE) + t;
#pragma unroll
    for (int j = 0; j < PPT; j++) {
        px[j] = xb[base + j * T];
        py[j] = xb[N + base + j * T];
        pz[j] = xb[2 * N + base + j * T];
        pd[j] = __int_as_float(0x7f800000);  // +inf
    }

    int cur = 0;
    float cx = xb[0], cy = xb[N], cz = xb[2 * N];

    for (int s = 0; s < K; s++) {
        if (r == 0 && t == 0) g_fps_idx[b * K + s] = cur;

        // ---- distance update + thread-local argmax (exact mul/add, no FMA) ----
        unsigned bestd = 0; int besti = 0x7fffffff;
        float bx = 0.f, by = 0.f, bz = 0.f;
#pragma unroll
        for (int j = 0; j < PPT; j++) {
            float dx = __fadd_rn(px[j], -cx);
            float dy = __fadd_rn(py[j], -cy);
            float dz = __fadd_rn(pz[j], -cz);
            float d2 = __fadd_rn(__fadd_rn(__fmul_rn(dx, dx), __fmul_rn(dy, dy)),
                                 __fmul_rn(dz, dz));
            float nd = fminf(pd[j], d2);
            pd[j] = nd;
            unsigned db = __float_as_uint(nd);   // dists >= 0: bits are order-isomorphic
            if (j == 0) {
                bestd = db; besti = base; bx = px[0]; by = py[0]; bz = pz[0];
            } else if (db > bestd) {             // strict > keeps lowest idx in-thread
                bestd = db; besti = base + j * T;
                bx = px[j]; by = py[j]; bz = pz[j];
            }
        }

        // ---- warp reduce: max dist, tie-break min index ----
        unsigned wm = __reduce_max_sync(0xffffffffu, bestd);
        int cand = (bestd == wm) ? besti : 0x7fffffff;
        int wi = __reduce_min_sync(0xffffffffu, cand);
        unsigned own = __ballot_sync(0xffffffffu, cand == wi);
        int src = __ffs(own) - 1;
        bx = __shfl_sync(0xffffffffu, bx, src);
        by = __shfl_sync(0xffffffffu, by, src);
        bz = __shfl_sync(0xffffffffu, bz, src);
        if (lane == 0) {
            s_warp[w].d = wm; s_warp[w].i = wi;
            s_warp[w].x = bx; s_warp[w].y = by; s_warp[w].z = bz;
        }
        __syncthreads();

        const int par = s & 1;
        // ---- block reduce (warp 0) + broadcast CTA winner to all cluster CTAs ----
        if (w == 0) {
            unsigned d; int i; float x, y, z;
            if (lane < NW) {
                d = s_warp[lane].d; i = s_warp[lane].i;
                x = s_warp[lane].x; y = s_warp[lane].y; z = s_warp[lane].z;
            } else {
                d = 0; i = 0x7fffffff; x = 0.f; y = 0.f; z = 0.f;
            }
            unsigned m2 = __reduce_max_sync(0xffffffffu, d);
            int c2 = (d == m2) ? i : 0x7fffffff;
            int i2 = __reduce_min_sync(0xffffffffu, c2);
            unsigned own2 = __ballot_sync(0xffffffffu, c2 == i2);
            int s2 = __ffs(own2) - 1;
            x = __shfl_sync(0xffffffffu, x, s2);
            y = __shfl_sync(0xffffffffu, y, s2);
            z = __shfl_sync(0xffffffffu, z, s2);
            if (lane < CSIZE) {
                // lane q writes this CTA's winner into CTA q's slot[par][r]
                unsigned la = smem_u32(&s_cl[par][r]);
                unsigned ra = mapa_u32(la, (unsigned)lane);
                st_cluster_u32(ra + 0,  m2);
                st_cluster_u32(ra + 4,  (unsigned)i2);
                st_cluster_u32(ra + 8,  __float_as_uint(x));
                st_cluster_u32(ra + 12, __float_as_uint(y));
                st_cluster_u32(ra + 16, __float_as_uint(z));
            }
        }
        cluster_sync_all();   // release DSMEM writes / acquire for reads

        // ---- every thread picks the global winner from CSIZE candidates ----
        unsigned gd = s_cl[par][0].d; int gi = s_cl[par][0].i;
        float gx = s_cl[par][0].x, gy = s_cl[par][0].y, gz = s_cl[par][0].z;
#pragma unroll
        for (int q = 1; q < CSIZE; q++) {
            unsigned qd = s_cl[par][q].d; int qi = s_cl[par][q].i;
            bool better = (qd > gd) || (qd == gd && qi < gi);
            if (better) {
                gd = qd; gi = qi;
                gx = s_cl[par][q].x; gy = s_cl[par][q].y; gz = s_cl[par][q].z;
            }
        }
        cur = gi; cx = gx; cy = gy; cz = gz;
    }
}

// out = [node_static (B,3,K)] ++ [node_feature (B,C,K)], row-major, fp32
__global__ void __launch_bounds__(K)
gather_kernel(const float* __restrict__ xyz, const float* __restrict__ feat,
              float* __restrict__ out) {
    const int b = blockIdx.y;
    const int e = blockIdx.x;   // 0..2 -> xyz, 3..130 -> feature channel e-3
    const int k = threadIdx.x;
    const int id = g_fps_idx[b * K + k];
    if (e < 3) {
        float v = xyz[(size_t)b * 3 * N + (size_t)e * N + id];
        out[((size_t)(b * 3 + e)) * K + k] = v;
    } else {
        const int c = e - 3;
        float v = feat[(size_t)b * C * N + (size_t)c * N + id];
        out[(size_t)B * 3 * K + ((size_t)(b * C + c)) * K + k] = v;
    }
}

extern "C" void kernel_launch(void* const* d_in, const int* in_sizes, int n_in,
                              void* d_out, int out_size) {
    const float* xyz  = (const float*)d_in[0];   // [B,3,N] fp32
    const float* feat = (const float*)d_in[1];   // [B,C,N] fp32
    float* out = (float*)d_out;

    fps_kernel<<<B * CSIZE, T>>>(xyz);
    gather_kernel<<<dim3(3 + C, B), K>>>(xyz, feat, out);
}

// round 2
// speedup vs baseline: 1.5010x; 1.5010x over previous
#include <cuda_runtime.h>
#include <cstdint>

#define B 8
#define N 32768
#define K 1024
#define C 128
#define CSIZE 8                  // CTAs per cluster (one cluster per batch)
#define T 512                    // threads per CTA
#define PPT 8                    // points per thread
#define NW 16                    // warps per CTA
#define FULL 0xffffffffu
#define TXB 192                  // 8 CTAs x 3 st.async.b64 = 8*24 bytes

typedef unsigned long long u64;

// FPS-selected indices, [B][K]
__device__ int g_fps_idx[B * K];

struct alignas(8) Slot {
    unsigned d;    // +0  fp32 bits of min-dist (nonneg -> uint order-isomorphic)
    int i;         // +4  point index
    float x, y;    // +8, +12
    float z;       // +16
    unsigned pad;  // +20
};

// ---------------- PTX helpers ----------------
__device__ __forceinline__ unsigned smem_u32(const void* p) {
    return (unsigned)__cvta_generic_to_shared(p);
}
__device__ __forceinline__ unsigned mapa_u32(unsigned addr, unsigned rank) {
    unsigned r;
    asm("mapa.shared::cluster.u32 %0, %1, %2;" : "=r"(r) : "r"(addr), "r"(rank));
    return r;
}
__device__ __forceinline__ u64 pk2f(float lo, float hi) {
    u64 v; asm("mov.b64 %0, {%1, %2};" : "=l"(v) : "f"(lo), "f"(hi)); return v;
}
__device__ __forceinline__ u64 pk2u(unsigned lo, unsigned hi) {
    u64 v; asm("mov.b64 %0, {%1, %2};" : "=l"(v) : "r"(lo), "r"(hi)); return v;
}
__device__ __forceinline__ void upk2f(float& lo, float& hi, u64 v) {
    asm("mov.b64 {%0, %1}, %2;" : "=f"(lo), "=f"(hi) : "l"(v));
}
__device__ __forceinline__ u64 addx2(u64 a, u64 b) {
    u64 r; asm("add.rn.f32x2 %0, %1, %2;" : "=l"(r) : "l"(a), "l"(b)); return r;
}
__device__ __forceinline__ u64 mulx2(u64 a, u64 b) {
    u64 r; asm("mul.rn.f32x2 %0, %1, %2;" : "=l"(r) : "l"(a), "l"(b)); return r;
}
__device__ __forceinline__ void mbar_init(unsigned bar, unsigned cnt) {
    asm volatile("mbarrier.init.shared.b64 [%0], %1;" :: "r"(bar), "r"(cnt) : "memory");
}
__device__ __forceinline__ void mbar_expect(unsigned bar, unsigned tx) {
    asm volatile("mbarrier.arrive.expect_tx.shared.b64 _, [%0], %1;"
                 :: "r"(bar), "r"(tx) : "memory");
}
__device__ __forceinline__ void st_async64(unsigned raddr, u64 v, unsigned rbar) {
    asm volatile(
        "st.async.shared::cluster.mbarrier::complete_tx::bytes.b64 [%0], %1, [%2];"
        :: "r"(raddr), "l"(v), "r"(rbar) : "memory");
}
__device__ __forceinline__ void mbar_wait(unsigned bar, unsigned ph) {
    asm volatile(
        "{\n\t"
        ".reg .pred P;\n\t"
        "WL_%=:\n\t"
        "mbarrier.try_wait.parity.acquire.cluster.shared::cta.b64 P, [%0], %1, 0x989680;\n\t"
        "@P bra WD_%=;\n\t"
        "bra WL_%=;\n\t"
        "WD_%=:\n\t"
        "}"
        :: "r"(bar), "r"(ph) : "memory");
}
__device__ __forceinline__ void cluster_sync_all() {
    asm volatile("barrier.cluster.arrive.aligned;" ::: "memory");
    asm volatile("barrier.cluster.wait.aligned;" ::: "memory");
}
__device__ __forceinline__ u64 sel4(const u64 a0, const u64 a1, const u64 a2,
                                    const u64 a3, int p) {
    u64 lo = (p & 1) ? a1 : a0;
    u64 hi = (p & 1) ? a3 : a2;
    return (p & 2) ? hi : lo;
}

__global__ void __cluster_dims__(CSIZE, 1, 1) __launch_bounds__(T, 1)
fps_kernel(const float* __restrict__ xyz) {
    __shared__ Slot s_warp[NW];
    __shared__ Slot s_cl[2][CSIZE];   // double-buffered cross-CTA candidate slots
    __shared__ u64 s_bar[2];          // double-buffered mbarriers

    const int t = threadIdx.x;
    const int lane = t & 31;
    const int w = t >> 5;
    const int blk = blockIdx.x;
    const int b = blk / CSIZE;       // batch
    const int r = blk % CSIZE;       // cluster rank

    const float* xb = xyz + (size_t)b * 3 * N;

    // Register-resident packed point slice + running scalar min-dist
    u64 PX[4], PY[4], PZ[4];
    float pd[PPT];
    const int base = r * (N / CSIZE) + t;
#pragma unroll
    for (int p = 0; p < 4; p++) {
        PX[p] = pk2f(xb[base + (2 * p) * T],         xb[base + (2 * p + 1) * T]);
        PY[p] = pk2f(xb[N + base + (2 * p) * T],     xb[N + base + (2 * p + 1) * T]);
        PZ[p] = pk2f(xb[2 * N + base + (2 * p) * T], xb[2 * N + base + (2 * p + 1) * T]);
    }
#pragma unroll
    for (int j = 0; j < PPT; j++) pd[j] = __int_as_float(0x7f800000);  // +inf

    const unsigned bar0 = smem_u32(&s_bar[0]);
    const unsigned bar1 = smem_u32(&s_bar[1]);
    if (t == 0) { mbar_init(bar0, 1); mbar_init(bar1, 1); }
    __syncthreads();
    // Arm both barriers' first phases BEFORE any remote can complete_tx
    // (remotes can only st.async after cluster_sync, which needs our arrive,
    //  which follows these expects in thread 0's program order).
    if (t == 0) { mbar_expect(bar0, TXB); mbar_expect(bar1, TXB); }
    cluster_sync_all();

    int cur = 0;
    float cx = xb[0], cy = xb[N], cz = xb[2 * N];

    for (int s = 0; s < K; s++) {
        if (r == 0 && t == 0) g_fps_idx[b * K + s] = cur;

        // ---- packed distance update + thread-local argmax (exact .rn mul/add) ----
        const u64 nx = pk2f(-cx, -cx);
        const u64 ny = pk2f(-cy, -cy);
        const u64 nz = pk2f(-cz, -cz);
        unsigned bestd = 0; int bestj = 0;
#pragma unroll
        for (int p = 0; p < 4; p++) {
            u64 dx = addx2(PX[p], nx);
            u64 dy = addx2(PY[p], ny);
            u64 dz = addx2(PZ[p], nz);
            u64 d2 = addx2(addx2(mulx2(dx, dx), mulx2(dy, dy)), mulx2(dz, dz));
            float da, db; upk2f(da, db, d2);
            float n0 = fminf(pd[2 * p], da);     pd[2 * p] = n0;
            unsigned u0 = __float_as_uint(n0);
            if (u0 > bestd) { bestd = u0; bestj = 2 * p; }       // strict > -> min idx
            float n1 = fminf(pd[2 * p + 1], db); pd[2 * p + 1] = n1;
            unsigned u1 = __float_as_uint(n1);
            if (u1 > bestd) { bestd = u1; bestj = 2 * p + 1; }
        }
        // resolve winner coords once (3-bit bestj select tree)
        {
            const int pp = bestj >> 1;
            u64 sx = sel4(PX[0], PX[1], PX[2], PX[3], pp);
            u64 sy = sel4(PY[0], PY[1], PY[2], PY[3], pp);
            u64 sz = sel4(PZ[0], PZ[1], PZ[2], PZ[3], pp);
            float xl, xh, yl, yh, zl, zh;
            upk2f(xl, xh, sx); upk2f(yl, yh, sy); upk2f(zl, zh, sz);
            const bool hi = bestj & 1;
            float bx = hi ? xh : xl;
            float by = hi ? yh : yl;
            float bz = hi ? zh : zl;
            const int besti = base + (bestj << 9);   // bestj * T

            // ---- warp reduce: max dist, tie-break min index ----
            unsigned wm = __reduce_max_sync(FULL, bestd);
            int cand = (bestd == wm) ? besti : 0x7fffffff;
            int wi = __reduce_min_sync(FULL, cand);
            unsigned own = __ballot_sync(FULL, cand == wi);
            int src = __ffs(own) - 1;
            bx = __shfl_sync(FULL, bx, src);
            by = __shfl_sync(FULL, by, src);
            bz = __shfl_sync(FULL, bz, src);
            if (lane == 0) {
                s_warp[w].d = wm; s_warp[w].i = wi;
                s_warp[w].x = bx; s_warp[w].y = by; s_warp[w].z = bz;
            }
        }
        __syncthreads();

        const int par = s & 1;
        const unsigned ph = (unsigned)((s >> 1) & 1);
        const unsigned barp = par ? bar1 : bar0;

        // ---- block reduce (warp 0) + st.async CTA winner to every cluster CTA ----
        if (w == 0) {
            unsigned d; int i; float x, y, z;
            if (lane < NW) {
                d = s_warp[lane].d; i = s_warp[lane].i;
                x = s_warp[lane].x; y = s_warp[lane].y; z = s_warp[lane].z;
            } else {
                d = 0; i = 0x7fffffff; x = 0.f; y = 0.f; z = 0.f;
            }
            unsigned m2 = __reduce_max_sync(FULL, d);
            int c2 = (d == m2 && lane < NW) ? i : 0x7fffffff;
            int i2 = __reduce_min_sync(FULL, c2);
            unsigned own2 = __ballot_sync(FULL, c2 == i2);
            int s2 = __ffs(own2) - 1;
            x = __shfl_sync(FULL, x, s2);
            y = __shfl_sync(FULL, y, s2);
            z = __shfl_sync(FULL, z, s2);
            if (lane < CSIZE) {
                // lane q delivers this CTA's winner into CTA q's slot[par][r],
                // completing on CTA q's barrier[par]
                unsigned la = smem_u32(&s_cl[par][r]);
                unsigned ra = mapa_u32(la, (unsigned)lane);
                unsigned rb = mapa_u32(barp, (unsigned)lane);
                st_async64(ra + 0,  pk2u(m2, (unsigned)i2), rb);
                st_async64(ra + 8,  pk2f(x, y),             rb);
                st_async64(ra + 16, pk2f(z, 0.f),           rb);
            }
        }

        // ---- wait for all 8 CTAs' candidates, then re-arm this buffer for s+2 ----
        mbar_wait(barp, ph);
        if (t == 0) mbar_expect(barp, TXB);

        // ---- warp-cooperative global winner (lanes 0..7 own one slot each) ----
        {
            unsigned d8 = 0; int i8 = 0x7fffffff; float fx = 0.f, fy = 0.f, fz = 0.f;
            if (lane < CSIZE) {
                const Slot& sl = s_cl[par][lane];
                d8 = sl.d; i8 = sl.i; fx = sl.x; fy = sl.y; fz = sl.z;
            }
            unsigned gm = __reduce_max_sync(FULL, d8);
            int c8 = (d8 == gm && lane < CSIZE) ? i8 : 0x7fffffff;
            int gi = __reduce_min_sync(FULL, c8);
            unsigned ow = __ballot_sync(FULL, c8 == gi);
            int sr = __ffs(ow) - 1;
            cx = __shfl_sync(FULL, fx, sr);
            cy = __shfl_sync(FULL, fy, sr);
            cz = __shfl_sync(FULL, fz, sr);
            cur = gi;
        }
    }
    cluster_sync_all();   // no CTA exits while peers may still touch its smem
}

// out = [node_static (B,3,K)] ++ [node_feature (B,C,K)], row-major, fp32
__global__ void __launch_bounds__(K)
gather_kernel(const float* __restrict__ xyz, const float* __restrict__ feat,
              float* __restrict__ out) {
    const int b = blockIdx.y;
    const int e = blockIdx.x;   // 0..2 -> xyz, 3..130 -> feature channel e-3
    const int k = threadIdx.x;
    const int id = g_fps_idx[b * K + k];
    if (e < 3) {
        out[((size_t)(b * 3 + e)) * K + k] =
            xyz[(size_t)b * 3 * N + (size_t)e * N + id];
    } else {
        const int c = e - 3;
        out[(size_t)B * 3 * K + ((size_t)(b * C + c)) * K + k] =
            feat[(size_t)b * C * N + (size_t)c * N + id];
    }
}

extern "C" void kernel_launch(void* const* d_in, const int* in_sizes, int n_in,
                              void* d_out, int out_size) {
    const float* xyz  = (const float*)d_in[0];   // [B,3,N] fp32
    const float* feat = (const float*)d_in[1];   // [B,C,N] fp32
    float* out = (float*)d_out;

    fps_kernel<<<B * CSIZE, T>>>(xyz);
    gather_kernel<<<dim3(3 + C, B), K>>>(xyz, feat, out);
}